// round 9
// baseline (speedup 1.0000x reference)
#include <cuda_runtime.h>
#include <cuda_bf16.h>
#include <cstdint>

// Shapes (fixed by the problem)
#define B_   32
#define H_   8
#define C_   64
#define L_   1024
#define HC_  512          // H_*C_
#define K_   6            // int(log(1024)) = 6
#define G_   32           // row-groups per batch in stage-1 reduction
#define RPG_ 16           // rows per group (HC_/G_)

// k_agg tiling
#define TROWS 4           // rows per block (32KB smem with duplication)

// Scratch (no allocations allowed -> __device__ globals)
__device__ float g_partial[B_ * G_ * L_];   // 4 MB
__device__ int   g_idx[K_];
__device__ float g_wts[B_ * K_];

// ---------------------------------------------------------------------------
// Kernel 1: partial reduce of corr over 16-row groups, float4-vectorized.
// grid (B_, G_) = 1024 blocks, 256 threads -> ~4096 warps chip-wide.
// ---------------------------------------------------------------------------
__global__ __launch_bounds__(256) void k_partial(const float* __restrict__ corr) {
    const int b = blockIdx.x;
    const int g = blockIdx.y;
    const int t = threadIdx.x;
    const float4* __restrict__ base =
        reinterpret_cast<const float4*>(corr) +
        ((size_t)b * HC_ + (size_t)g * RPG_) * (L_ / 4) + t;

    float4 a0 = make_float4(0.f, 0.f, 0.f, 0.f);
    float4 a1 = make_float4(0.f, 0.f, 0.f, 0.f);
#pragma unroll
    for (int r = 0; r < RPG_; r += 2) {
        float4 v0 = base[(size_t)r * (L_ / 4)];
        float4 v1 = base[(size_t)(r + 1) * (L_ / 4)];
        a0.x += v0.x; a0.y += v0.y; a0.z += v0.z; a0.w += v0.w;
        a1.x += v1.x; a1.y += v1.y; a1.z += v1.z; a1.w += v1.w;
    }
    float4 s;
    s.x = a0.x + a1.x; s.y = a0.y + a1.y; s.z = a0.z + a1.z; s.w = a0.w + a1.w;
    reinterpret_cast<float4*>(g_partial)[((size_t)(b * G_ + g)) * (L_ / 4) + t] = s;
}

// ---------------------------------------------------------------------------
// Kernel 2: single block, 1024 threads. Combine the 32 per-batch partials
// per column (ranking criterion = column sum, monotone to the mean), top-6
// via argmax-iterate with smaller-index tie-break (same SET as lax.top_k;
// order irrelevant: the softmax-weighted sum is permutation invariant),
// then per-batch softmax over mean_value[b, idx].
// ---------------------------------------------------------------------------
__global__ __launch_bounds__(1024) void k_topk_softmax() {
    __shared__ float sm[L_];
    __shared__ float wval[32];
    __shared__ int   widx[32];
    __shared__ int   s_idx[K_];

    const int t   = threadIdx.x;     // == l
    const int wid = t >> 5;
    const int lid = t & 31;

    // combine all B_*G_ partials per column (coalesced L2 reads)
    {
        float s = 0.f;
#pragma unroll 8
        for (int i = 0; i < B_ * G_; ++i)
            s += g_partial[(size_t)i * L_ + t];
        sm[t] = s;
    }
    __syncthreads();

    for (int k = 0; k < K_; ++k) {
        float bv = sm[t];
        int   bi = t;
#pragma unroll
        for (int off = 16; off > 0; off >>= 1) {
            float v2 = __shfl_down_sync(0xffffffffu, bv, off);
            int   i2 = __shfl_down_sync(0xffffffffu, bi, off);
            if (v2 > bv || (v2 == bv && i2 < bi)) { bv = v2; bi = i2; }
        }
        if (lid == 0) { wval[wid] = bv; widx[wid] = bi; }
        __syncthreads();
        if (t == 0) {
            float fv = wval[0]; int fi = widx[0];
#pragma unroll
            for (int w = 1; w < 32; ++w) {
                if (wval[w] > fv || (wval[w] == fv && widx[w] < fi)) {
                    fv = wval[w]; fi = widx[w];
                }
            }
            s_idx[k] = fi;
            g_idx[k] = fi;
            sm[fi]   = -3.0e38f;
        }
        __syncthreads();
    }

    // per-batch softmax over mean_value[b, idx[0..5]]
    if (t < B_) {
        const int b = t;
        float w[K_];
        float m = -3.0e38f;
#pragma unroll
        for (int k = 0; k < K_; ++k) {
            const int idx = s_idx[k];
            float p = 0.f;
#pragma unroll
            for (int g = 0; g < G_; ++g)
                p += g_partial[(size_t)(b * G_ + g) * L_ + idx];
            w[k] = p * (1.0f / (float)HC_);
            m = fmaxf(m, w[k]);
        }
        float sum = 0.f;
#pragma unroll
        for (int k = 0; k < K_; ++k) { w[k] = __expf(w[k] - m); sum += w[k]; }
        const float inv = 1.0f / sum;
#pragma unroll
        for (int k = 0; k < K_; ++k) g_wts[b * K_ + k] = w[k] * inv;
    }
}

// ---------------------------------------------------------------------------
// Kernel 3: delays aggregation, instruction-minimal inner loop.
// Each row is staged DUPLICATED in smem (sv[x] = sv[x+L] = row[x]) so the
// circular index (l+i)&1023 becomes a plain s[l+i]: no AND, no per-access
// IADD. Six base pointers (srow + i_k + t) are hoisted per row; the inner
// loop is pure LDS [ptr + imm] + FFMA + one coalesced STG per j.
// TROWS=4 -> 32KB smem, ~87% occupancy, 4096 blocks.
// ---------------------------------------------------------------------------
__global__ __launch_bounds__(256) void k_agg(const float* __restrict__ values,
                                             float* __restrict__ out) {
    __shared__ float sv[TROWS * 2 * L_];    // 32 KB
    const int t    = threadIdx.x;
    const int row0 = blockIdx.x * TROWS;
    const int b    = row0 >> 9;             // row0 / (H_*C_)

    // stage TROWS rows, duplicated (independent LDG.128s -> MLP=4)
    const float4* __restrict__ src =
        reinterpret_cast<const float4*>(values + (size_t)row0 * L_);
    float4* sv4 = reinterpret_cast<float4*>(sv);
#pragma unroll
    for (int r = 0; r < TROWS; ++r) {
        float4 v = src[r * 256 + t];
        sv4[r * 512 + t]       = v;
        sv4[r * 512 + 256 + t] = v;
    }

    // broadcast weights + indices (L2-resident)
    const float w0 = g_wts[b * K_ + 0], w1 = g_wts[b * K_ + 1], w2 = g_wts[b * K_ + 2];
    const float w3 = g_wts[b * K_ + 3], w4 = g_wts[b * K_ + 4], w5 = g_wts[b * K_ + 5];
    const int   i0 = g_idx[0], i1 = g_idx[1], i2 = g_idx[2];
    const int   i3 = g_idx[3], i4 = g_idx[4], i5 = g_idx[5];

    __syncthreads();

#pragma unroll
    for (int r = 0; r < TROWS; ++r) {
        const float* srow = sv + r * 2 * L_;
        const float* p0 = srow + i0 + t;
        const float* p1 = srow + i1 + t;
        const float* p2 = srow + i2 + t;
        const float* p3 = srow + i3 + t;
        const float* p4 = srow + i4 + t;
        const float* p5 = srow + i5 + t;
        float* drow = out + (size_t)(row0 + r) * L_;
#pragma unroll
        for (int j = 0; j < 4; ++j) {
            const int off = j * 256;
            float acc;
            acc  = p0[off] * w0;
            acc += p1[off] * w1;
            acc += p2[off] * w2;
            acc += p3[off] * w3;
            acc += p4[off] * w4;
            acc += p5[off] * w5;
            drow[t + off] = acc;
        }
    }
}

// ---------------------------------------------------------------------------
extern "C" void kernel_launch(void* const* d_in, const int* in_sizes, int n_in,
                              void* d_out, int out_size) {
    const float* values = (const float*)d_in[0];
    const float* corr   = (const float*)d_in[1];
    float*       out    = (float*)d_out;

    dim3 g1(B_, G_);
    k_partial<<<g1, 256>>>(corr);
    k_topk_softmax<<<1, 1024>>>();
    k_agg<<<(B_ * H_ * C_) / TROWS, 256>>>(values, out);
}

// round 10
// speedup vs baseline: 1.9439x; 1.9439x over previous
#include <cuda_runtime.h>
#include <cuda_bf16.h>
#include <cstdint>

// Shapes (fixed by the problem)
#define B_   32
#define H_   8
#define C_   64
#define L_   1024
#define HC_  512          // H_*C_
#define K_   6            // int(log(1024)) = 6
#define G_   32           // row-groups per batch in stage-1 reduction
#define RPG_ 16           // rows per group (HC_/G_)
#define ROWS_PER_BLK 4    // k_agg rows per block

// Scratch (no allocations allowed -> __device__ globals)
__device__ float g_partial[B_ * G_ * L_];   // 4 MB
__device__ float g_meanv[B_ * L_];          // 128 KB
__device__ int   g_idx[K_];
__device__ float g_wts[B_ * K_];

// ---------------------------------------------------------------------------
// Kernel 1: partial reduce of corr over 16-row groups, float4-vectorized,
// 4 independent accumulators fully unrolled (16 LDG.128 batches in flight).
// grid (B_, G_) = 1024 blocks, 256 threads.
// ---------------------------------------------------------------------------
__global__ __launch_bounds__(256) void k_partial(const float* __restrict__ corr) {
    const int b = blockIdx.x;
    const int g = blockIdx.y;
    const int t = threadIdx.x;
    const float4* __restrict__ base =
        reinterpret_cast<const float4*>(corr) +
        ((size_t)b * HC_ + (size_t)g * RPG_) * (L_ / 4) + t;

    float4 a[4];
#pragma unroll
    for (int m = 0; m < 4; ++m) a[m] = make_float4(0.f, 0.f, 0.f, 0.f);

#pragma unroll
    for (int r = 0; r < RPG_; r += 4) {
#pragma unroll
        for (int m = 0; m < 4; ++m) {
            float4 v = base[(size_t)(r + m) * (L_ / 4)];
            a[m].x += v.x; a[m].y += v.y; a[m].z += v.z; a[m].w += v.w;
        }
    }
    a[0].x += a[2].x; a[0].y += a[2].y; a[0].z += a[2].z; a[0].w += a[2].w;
    a[1].x += a[3].x; a[1].y += a[3].y; a[1].z += a[3].z; a[1].w += a[3].w;
    float4 s;
    s.x = a[0].x + a[1].x; s.y = a[0].y + a[1].y;
    s.z = a[0].z + a[1].z; s.w = a[0].w + a[1].w;
    reinterpret_cast<float4*>(g_partial)[((size_t)(b * G_ + g)) * (L_ / 4) + t] = s;
}

// ---------------------------------------------------------------------------
// Kernel 2: combine partials -> mean_value[b,l]. grid (B_,4), 256 threads.
// ---------------------------------------------------------------------------
__global__ __launch_bounds__(256) void k_combine() {
    const int b = blockIdx.x;
    const int l = blockIdx.y * 256 + threadIdx.x;
    float s = 0.f;
#pragma unroll
    for (int g = 0; g < G_; ++g)
        s += g_partial[((size_t)b * G_ + g) * L_ + l];
    g_meanv[(size_t)b * L_ + l] = s * (1.0f / (float)HC_);
}

// ---------------------------------------------------------------------------
// Kernel 3: single block, 256 threads. batch-mean, top-6 (argmax iterate with
// smaller-index tie-break -> same SET as lax.top_k; order irrelevant since the
// final softmax-weighted sum is permutation invariant), per-batch softmax.
// Only reads the 128 KB meanv (L2-resident).
// ---------------------------------------------------------------------------
__global__ __launch_bounds__(256) void k_topk_softmax() {
    __shared__ float sm[L_];
    __shared__ float wval[8];
    __shared__ int   widx[8];
    __shared__ int   s_idx[K_];

    const int t   = threadIdx.x;
    const int wid = t >> 5;
    const int lid = t & 31;

#pragma unroll
    for (int j = 0; j < 4; ++j) {
        const int l = t + j * 256;
        float s = 0.f;
#pragma unroll 8
        for (int b = 0; b < B_; ++b) s += g_meanv[(size_t)b * L_ + l];
        sm[l] = s;
    }
    __syncthreads();

    for (int k = 0; k < K_; ++k) {
        float bv = -3.0e38f; int bi = 0x7fffffff;
#pragma unroll
        for (int j = 0; j < 4; ++j) {
            const int l = t + j * 256;
            const float v = sm[l];
            if (v > bv || (v == bv && l < bi)) { bv = v; bi = l; }
        }
#pragma unroll
        for (int off = 16; off > 0; off >>= 1) {
            float v2 = __shfl_down_sync(0xffffffffu, bv, off);
            int   i2 = __shfl_down_sync(0xffffffffu, bi, off);
            if (v2 > bv || (v2 == bv && i2 < bi)) { bv = v2; bi = i2; }
        }
        if (lid == 0) { wval[wid] = bv; widx[wid] = bi; }
        __syncthreads();
        if (t == 0) {
            float fv = wval[0]; int fi = widx[0];
#pragma unroll
            for (int w = 1; w < 8; ++w) {
                if (wval[w] > fv || (wval[w] == fv && widx[w] < fi)) {
                    fv = wval[w]; fi = widx[w];
                }
            }
            s_idx[k] = fi;
            g_idx[k] = fi;
            sm[fi]   = -3.0e38f;
        }
        __syncthreads();
    }

    if (t < B_) {
        const int b = t;
        float w[K_];
        float m = -3.0e38f;
#pragma unroll
        for (int k = 0; k < K_; ++k) {
            w[k] = g_meanv[(size_t)b * L_ + s_idx[k]];
            m = fmaxf(m, w[k]);
        }
        float sum = 0.f;
#pragma unroll
        for (int k = 0; k < K_; ++k) { w[k] = __expf(w[k] - m); sum += w[k]; }
        const float inv = 1.0f / sum;
#pragma unroll
        for (int k = 0; k < K_; ++k) g_wts[b * K_ + k] = w[k] * inv;
    }
}

// ---------------------------------------------------------------------------
// Kernel 4: delays aggregation — exact R6 configuration (measured 25.3us).
// 4 rows per block staged via 4 independent LDG.128 per thread, one sync,
// out[l] = sum_k sv[(l+idx_k)&1023] * w[b,k]. LDS stride-1 across lanes
// (conflict-free, bytes-minimal 24B/output); stores fully coalesced.
// ---------------------------------------------------------------------------
__global__ __launch_bounds__(256) void k_agg(const float* __restrict__ values,
                                             float* __restrict__ out) {
    __shared__ float sv[ROWS_PER_BLK * L_];
    const int t    = threadIdx.x;
    const int row0 = blockIdx.x * ROWS_PER_BLK;      // 4 rows, same batch b
    const int b    = row0 >> 9;                      // row0 / (H_*C_)

    const float4* __restrict__ src =
        reinterpret_cast<const float4*>(values + (size_t)row0 * L_);
    float4* sv4 = reinterpret_cast<float4*>(sv);
#pragma unroll
    for (int j = 0; j < 4; ++j) sv4[t + j * 256] = src[t + j * 256];

    const float w0 = g_wts[b * K_ + 0], w1 = g_wts[b * K_ + 1], w2 = g_wts[b * K_ + 2];
    const float w3 = g_wts[b * K_ + 3], w4 = g_wts[b * K_ + 4], w5 = g_wts[b * K_ + 5];
    const int   i0 = g_idx[0], i1 = g_idx[1], i2 = g_idx[2];
    const int   i3 = g_idx[3], i4 = g_idx[4], i5 = g_idx[5];

    __syncthreads();

    float* dst = out + (size_t)row0 * L_;
#pragma unroll
    for (int r = 0; r < ROWS_PER_BLK; ++r) {
        const float* s = sv + r * L_;
        float* drow = dst + (size_t)r * L_;
#pragma unroll
        for (int j = 0; j < 4; ++j) {
            const int l = t + j * 256;
            float acc;
            acc  = s[(l + i0) & (L_ - 1)] * w0;
            acc += s[(l + i1) & (L_ - 1)] * w1;
            acc += s[(l + i2) & (L_ - 1)] * w2;
            acc += s[(l + i3) & (L_ - 1)] * w3;
            acc += s[(l + i4) & (L_ - 1)] * w4;
            acc += s[(l + i5) & (L_ - 1)] * w5;
            drow[l] = acc;
        }
    }
}

// ---------------------------------------------------------------------------
extern "C" void kernel_launch(void* const* d_in, const int* in_sizes, int n_in,
                              void* d_out, int out_size) {
    const float* values = (const float*)d_in[0];
    const float* corr   = (const float*)d_in[1];
    float*       out    = (float*)d_out;

    dim3 g1(B_, G_);
    k_partial<<<g1, 256>>>(corr);
    dim3 g2(B_, 4);
    k_combine<<<g2, 256>>>();
    k_topk_softmax<<<1, 256>>>();
    k_agg<<<(B_ * H_ * C_) / ROWS_PER_BLK, 256>>>(values, out);
}